// round 16
// baseline (speedup 1.0000x reference)
#include <cuda_runtime.h>

// ---------------------------------------------------------------------------
// SphericalExpansion:
//  - k_fill: 2 pairs/thread (int2 index loads, 2 independent gather chains),
//    filters r >= R_CUT (fc==0 => exact zero), stores (dx,dy,dz,species).
//  - k_acc: TWO atoms per warp (lanes 0-15 -> atom A, 16-31 -> atom B),
//    16-pair tiles; Y/F streamed to smem in float4 chunks as computed to cut
//    register pressure; __launch_bounds__(256,6) forces ~40 regs -> 6 blk/SM.
//    All 32 lanes accumulate both atoms' outputs. Self-resets g_count.
// ---------------------------------------------------------------------------

constexpr int MAX_ATOMS = 20000;
constexpr int CAP       = 96;       // mean filtered count ~16; huge margin
constexpr float R_CUT_F = 5.0f;

__device__ int    g_count[MAX_ATOMS];        // zero-initialized at module load
__device__ float4 g_vec[MAX_ATOMS * CAP];    // (dx,dy,dz, species-as-float)

__global__ void k_fill(const float* __restrict__ pos,
                       const int*   __restrict__ centers,
                       const int*   __restrict__ neighbors,
                       const int*   __restrict__ species, int P)
{
    const int t  = blockIdx.x * blockDim.x + threadIdx.x;
    const int p0 = t * 2;
    if (p0 >= P) return;

    // 8B index loads: two pairs' indices in one LDG each
    const int2 c2 = *(const int2*)&centers[p0];
    const int2 n2 = *(const int2*)&neighbors[p0];

    // pair 0
    {
        const float dx = __ldg(&pos[3 * n2.x + 0]) - __ldg(&pos[3 * c2.x + 0]);
        const float dy = __ldg(&pos[3 * n2.x + 1]) - __ldg(&pos[3 * c2.x + 1]);
        const float dz = __ldg(&pos[3 * n2.x + 2]) - __ldg(&pos[3 * c2.x + 2]);
        const float r2 = dx * dx + dy * dy + dz * dz;
        if (r2 < R_CUT_F * R_CUT_F) {
            const int slot = atomicAdd(&g_count[c2.x], 1);
            if (slot < CAP) {
                const int s = __ldg(&species[n2.x]);
                g_vec[c2.x * CAP + slot] = make_float4(dx, dy, dz, __int_as_float(s));
            }
        }
    }
    // pair 1
    if (p0 + 1 < P) {
        const float dx = __ldg(&pos[3 * n2.y + 0]) - __ldg(&pos[3 * c2.y + 0]);
        const float dy = __ldg(&pos[3 * n2.y + 1]) - __ldg(&pos[3 * c2.y + 1]);
        const float dz = __ldg(&pos[3 * n2.y + 2]) - __ldg(&pos[3 * c2.y + 2]);
        const float r2 = dx * dx + dy * dy + dz * dz;
        if (r2 < R_CUT_F * R_CUT_F) {
            const int slot = atomicAdd(&g_count[c2.y], 1);
            if (slot < CAP) {
                const int s = __ldg(&species[n2.y]);
                g_vec[c2.y * CAP + slot] = make_float4(dx, dy, dz, __int_as_float(s));
            }
        }
    }
}

__global__ __launch_bounds__(256, 6) void k_acc(
    const float* __restrict__ W,     // [2,4] row-major
    float*       __restrict__ out,   // [nAtoms, 16, 16]
    int nAtoms)
{
    // stride 20 floats: 16B-aligned rows, conflict-free lane-major writes,
    // broadcast reads (all lanes of a warp read the same row p).
    __shared__ __align__(16) float sY[8][32][20];
    __shared__ __align__(16) float sF[8][32][20];
    __shared__ float sW[8];

    if (threadIdx.x < 8) sW[threadIdx.x] = W[threadIdx.x];
    __syncthreads();

    const int w    = threadIdx.x >> 5;
    const int lane = threadIdx.x & 31;

    const int atomA = blockIdx.x * 16 + w * 2;   // two atoms per warp
    const int atomB = atomA + 1;
    if (atomA >= nAtoms) return;
    const bool hasB = (atomB < nAtoms);

    int cntA = g_count[atomA];
    int cntB = hasB ? g_count[atomB] : 0;
    if (lane == 0) g_count[atomA] = 0;           // self-reset for next launch
    if (lane == 1 && hasB) g_count[atomB] = 0;
    if (cntA > CAP) cntA = CAP;
    if (cntB > CAP) cntB = CAP;

    const int  half   = lane >> 4;               // 0 -> A pairs, 1 -> B pairs
    const int  hl     = lane & 15;
    const int  myAtom = half ? atomB : atomA;
    const int  myCnt  = half ? cntB : cntA;

    float accA[8], accB[8];
#pragma unroll
    for (int j = 0; j < 8; j++) { accA[j] = 0.0f; accB[j] = 0.0f; }

    // lane owns out elements e = lane*8+j of EACH atom:
    //   comp = lane>>1 (const), col = (lane&1)*8+j
    const int cidx  = lane >> 1;
    const int fbase = (lane & 1) << 3;

    // Radial recurrence: rad_n = G * E^n * K1^(n^2)
    const float K1 = __expf(-0.6530612244897959f);   // exp(-(32/49))
    const float K2 = K1 * K1;

    float* const myY = &sY[w][lane][0];
    float* const myF = &sF[w][lane][0];

    const int tiles = max((cntA + 15) >> 4, (cntB + 15) >> 4);

    for (int t = 0; t < tiles; t++) {
        const int base = t << 4;
        int mA = cntA - base; mA = mA < 0 ? 0 : (mA > 16 ? 16 : mA);
        int mB = cntB - base; mB = mB < 0 ? 0 : (mB > 16 ? 16 : mB);
        const int mrA = (mA + 7) & ~7;
        const int mrB = (mB + 7) & ~7;

        const int k = base + hl;
        if (k < myCnt) {
            const float4 v = __ldg(&g_vec[myAtom * CAP + k]);
            const float r2   = v.x * v.x + v.y * v.y + v.z * v.z + 1e-12f;
            const float rinv = rsqrtf(r2);
            const float r    = r2 * rinv;
            const float x = v.x * rinv, y = v.y * rinv, z = v.z * rinv;
            const float x2 = x * x, y2 = y * y, z2 = z * z;

            // Stream Y to smem in float4 chunks (keeps live set small)
            *(float4*)&myY[0] = make_float4(
                0.28209479177387814f,
                0.4886025119029199f * y,
                0.4886025119029199f * z,
                0.4886025119029199f * x);
            *(float4*)&myY[4] = make_float4(
                1.0925484305920792f * x * y,
                1.0925484305920792f * y * z,
                0.31539156525252005f * (3.0f * z2 - 1.0f),
                1.0925484305920792f * x * z);
            *(float4*)&myY[8] = make_float4(
                0.5462742152960396f * (x2 - y2),
                0.5900435899266435f * y * (3.0f * x2 - y2),
                2.890611442640554f  * x * y * z,
                0.4570457994644658f * y * (5.0f * z2 - 1.0f));
            *(float4*)&myY[12] = make_float4(
                0.3731763325901154f * z * (5.0f * z2 - 3.0f),
                0.4570457994644658f * x * (5.0f * z2 - 1.0f),
                1.445305721320277f  * z * (x2 - y2),
                0.5900435899266435f * x * (x2 - 3.0f * y2));

            // r < R_CUT guaranteed by k_fill filter
            const float fc = 0.5f * (__cosf(0.6283185307179586f * r) + 1.0f);

            const int   s  = __float_as_int(v.w);
            const float b0 = fc * sW[s];
            const float b1 = fc * sW[4 + s];

            float rads[8];
            float rad = __expf(-1.28f * r * r);                  // G
            float u   = __expf(1.8285714285714286f * r) * K1;    // E*K1
#pragma unroll
            for (int n = 0; n < 8; n++) {
                rads[n] = rad;
                rad *= u;
                u   *= K2;
            }
            *(float4*)&myF[0]  = make_float4(b0*rads[0], b0*rads[1], b0*rads[2], b0*rads[3]);
            *(float4*)&myF[4]  = make_float4(b0*rads[4], b0*rads[5], b0*rads[6], b0*rads[7]);
            *(float4*)&myF[8]  = make_float4(b1*rads[0], b1*rads[1], b1*rads[2], b1*rads[3]);
            *(float4*)&myF[12] = make_float4(b1*rads[4], b1*rads[5], b1*rads[6], b1*rads[7]);
        } else if (hl < (half ? mrB : mrA)) {
            // pad rows the 8-unrolled accumulator reads: finite zeros
            const float4 z4 = make_float4(0.f, 0.f, 0.f, 0.f);
#pragma unroll
            for (int j = 0; j < 4; j++) {
                *(float4*)&myY[4*j] = z4;
                *(float4*)&myF[4*j] = z4;
            }
        }
        __syncwarp();

        // all 32 lanes accumulate atom A over rows [0, mrA)
        for (int p0 = 0; p0 < mrA; p0 += 8) {
#pragma unroll
            for (int pp = 0; pp < 8; pp++) {
                const int p = p0 + pp;
                const float  yv = sY[w][p][cidx];
                const float4 fa = *(const float4*)&sF[w][p][fbase];
                const float4 fb = *(const float4*)&sF[w][p][fbase + 4];
                accA[0] += yv * fa.x;  accA[1] += yv * fa.y;
                accA[2] += yv * fa.z;  accA[3] += yv * fa.w;
                accA[4] += yv * fb.x;  accA[5] += yv * fb.y;
                accA[6] += yv * fb.z;  accA[7] += yv * fb.w;
            }
        }
        // all 32 lanes accumulate atom B over rows [16, 16+mrB)
        for (int p0 = 0; p0 < mrB; p0 += 8) {
#pragma unroll
            for (int pp = 0; pp < 8; pp++) {
                const int p = 16 + p0 + pp;
                const float  yv = sY[w][p][cidx];
                const float4 fa = *(const float4*)&sF[w][p][fbase];
                const float4 fb = *(const float4*)&sF[w][p][fbase + 4];
                accB[0] += yv * fa.x;  accB[1] += yv * fa.y;
                accB[2] += yv * fa.z;  accB[3] += yv * fa.w;
                accB[4] += yv * fb.x;  accB[5] += yv * fb.y;
                accB[6] += yv * fb.z;  accB[7] += yv * fb.w;
            }
        }
        __syncwarp();
    }

    float4* oA = (float4*)(out + (size_t)atomA * 256 + lane * 8);
    oA[0] = make_float4(accA[0], accA[1], accA[2], accA[3]);
    oA[1] = make_float4(accA[4], accA[5], accA[6], accA[7]);
    if (hasB) {
        float4* oB = (float4*)(out + (size_t)atomB * 256 + lane * 8);
        oB[0] = make_float4(accB[0], accB[1], accB[2], accB[3]);
        oB[1] = make_float4(accB[4], accB[5], accB[6], accB[7]);
    }
}

extern "C" void kernel_launch(void* const* d_in, const int* in_sizes, int n_in,
                              void* d_out, int out_size) {
    const float* pos       = (const float*)d_in[0];
    const float* W         = (const float*)d_in[1];
    const int*   centers   = (const int*)d_in[2];
    const int*   neighbors = (const int*)d_in[3];
    const int*   species   = (const int*)d_in[4];
    float*       out       = (float*)d_out;

    const int P      = in_sizes[2];
    const int nAtoms = in_sizes[4];

    const int threadsF = 256;
    const int pairsPerBlock = threadsF * 2;
    k_fill<<<(P + pairsPerBlock - 1) / pairsPerBlock, threadsF>>>(pos, centers, neighbors, species, P);
    k_acc<<<(nAtoms + 15) / 16, 256>>>(W, out, nAtoms);
}